// round 16
// baseline (speedup 1.0000x reference)
#include <cuda_runtime.h>
#include <math.h>

// ---- problem constants ----
#define NFFT      512
#define HOP       256
#define NBIN      19      // rfft bins 13..31  (400 <= f < 1000 Hz, df = 31.25)
#define BIN0      13
#define NANG      18001
#define MICS      4
#define NFRM      4       // EST_NUM frames, t = 120..123
#define SAMPLE_OFF 30464  // first sample used = 119*256
#define NTCK      (NFRM * MICS * NBIN)   // 304

#define NBLK      141
#define NTHR      128

// cross-block mailboxes (self-resetting each launch)
__device__ float2 gX[NTCK];
__device__ unsigned int g_cnt;    // DFT warps completed (0 at launch start)
__device__ unsigned int g_done;   // blocks past the poll

// ---- Hermitian-compact complex Jacobi helpers ----
// Pattern A: stored (u_{ip}, u_{iq}), i < p < q
#define OFF_A(U1R,U1I,U2R,U2I) { \
    float t1r =  cc*U1R + ser*U2R + sei*U2I; \
    float t1i =  cc*U1I + ser*U2I - sei*U2R; \
    float t2r = -ssn*U1R + cer*U2R + cei*U2I; \
    float t2i = -ssn*U1I + cer*U2I - cei*U2R; \
    U1R=t1r; U1I=t1i; U2R=t2r; U2I=t2i; }
// Pattern B: stored (u_{pi}, u_{qi}), p < q < i
#define OFF_B(U1R,U1I,U2R,U2I) { \
    float t1r =  cc*U1R + ser*U2R - sei*U2I; \
    float t1i =  cc*U1I + ser*U2I + sei*U2R; \
    float t2r = -ssn*U1R + cer*U2R - cei*U2I; \
    float t2i = -ssn*U1I + cer*U2I + cei*U2R; \
    U1R=t1r; U1I=t1i; U2R=t2r; U2I=t2i; }
// Pattern C: stored (u_{pi}, u_{iq}), p < i < q
#define OFF_C(U1R,U1I,U2R,U2I) { \
    float t1r =  cc*U1R + ser*U2R + sei*U2I; \
    float t1i =  cc*U1I - ser*U2I + sei*U2R; \
    float t2r = -ssn*U1R + cer*U2R + cei*U2I; \
    float t2i =  ssn*U1I + cer*U2I - cei*U2R; \
    U1R=t1r; U1I=t1i; U2R=t2r; U2I=t2i; }

// rotation on pair (p,q): DP,DQ diag; UR,UI = u_pq; OFF = two pair updates
#define ROTC(DP,DQ,UR,UI,OFF) do { \
    float gr=UR, gi=UI; \
    float g2=fmaf(gr,gr,gi*gi); \
    if (g2>=thr) { \
        float inv_g=rsqrtf(g2); float g=g2*inv_g; \
        float er=gr*inv_g, ei=gi*inv_g; \
        float tau=(DQ-DP)*(0.5f*inv_g); \
        float t2v=fmaf(tau,tau,1.f); float root=t2v*rsqrtf(t2v); \
        float tt=__fdividef((tau>=0.f)?-1.f:1.f, fabsf(tau)+root); \
        float cc=rsqrtf(fmaf(tt,tt,1.f)); float ssn=tt*cc; \
        float ser=ssn*er, sei=ssn*ei, cer=cc*er, cei=cc*ei; \
        float c2v=cc*cc, s2v=ssn*ssn, csg=2.f*cc*ssn*g; \
        float ndp = c2v*DP + csg + s2v*DQ; \
        float ndq = s2v*DP - csg + c2v*DQ; \
        DP=ndp; DQ=ndq; UR=0.f; UI=0.f; \
        OFF \
    } } while(0)

// ============================================================
// Single fused kernel: 141 blocks x 128 threads, all wave-1 resident.
//  phase 1: warps gw<304 do the windowed DFT -> gX, RED-count
//  phase 2: every block: thread0 volatile-polls count==304; warp 0
//           lanes 0..18 run compact Jacobi (eigenvalues only) +
//           polynomial noise projector -> sQ (shared)
//  phase 3: all threads evaluate their angle of the spectrum
//  tail:    last block resets mailboxes for the next graph replay
// ============================================================
__global__ void __launch_bounds__(NTHR, 1) k_music(const float* __restrict__ x,
                                                   float* __restrict__ out)
{
    __shared__ float sQ[NBIN * 8];
    const int tid = threadIdx.x;

    // ---------- phase 1: DFT ----------
    const int gw = blockIdx.x * (NTHR / 32) + (tid >> 5);
    const int l  = tid & 31;
    if (gw < NTCK) {
        const int t   = gw / (MICS * NBIN);
        const int rem = gw % (MICS * NBIN);
        const int c   = rem / NBIN;
        const int bin = (rem % NBIN) + BIN0;

        const float ANG = -0.012271846303085130f;          // -2*pi/512
        float c1, s1, cs, ss;
        __sincosf((float)((bin * l)  & 511) * ANG, &s1, &c1);
        __sincosf((float)((bin * 32) & 511) * ANG, &ss, &cs);

        const float* px = x + ((size_t)SAMPLE_OFF + (size_t)t * HOP) * MICS + c;

        float re = 0.f, im = 0.f;
        #pragma unroll
        for (int j = 0; j < 16; j++) {
            int n = l + 32 * j;
            float v = px[n * MICS] * __sinf((float)n * (float)(M_PI / 512.0));
            re = fmaf(v, c1, re);
            im = fmaf(v, s1, im);
            float cn = fmaf(c1, cs, -s1 * ss);
            float sn = fmaf(s1, cs,  c1 * ss);
            c1 = cn; s1 = sn;
        }
        #pragma unroll
        for (int off = 16; off; off >>= 1) {
            re += __shfl_down_sync(0xffffffffu, re, off);
            im += __shfl_down_sync(0xffffffffu, im, off);
        }
        if (l == 0) {
            gX[gw] = make_float2(re, im);
            __threadfence();
            atomicAdd(&g_cnt, 1u);   // result unused -> RED, ~1 cyc/op at L2
        }
    }

    // ---------- spec init (independent of gQ; overlaps the wait) ----------
    int a = blockIdx.x * NTHR + tid;
    float th = (-90.0f + 0.01f * (float)a) * 0.017453292519943295f;
    float st = __sinf(th);
    float base = (float)(2.0 * M_PI * 0.1 / 343.0) * st;
    float dphi = base * 31.25f;
    float phi0 = dphi * (float)BIN0;
    float s1a, c1a, sda, cda;
    __sincosf(phi0, &s1a, &c1a);
    __sincosf(dphi, &sda, &cda);

    // ---------- wait for all DFT warps ----------
    if (tid == 0) {
        while (*(volatile unsigned int*)&g_cnt < (unsigned)NTCK) __nanosleep(32);
    }
    __syncthreads();   // thread0's acquire-observation ordered before all reads

    // ---------- phase 2: eigen, lanes 0..18 of warp 0 ----------
    if (tid < NBIN) {
        const int f = tid;
        float xr[16], xi[16];
        #pragma unroll
        for (int i = 0; i < 16; i++) {
            float2 v = __ldcg(&gX[i * NBIN + f]);   // L2 read, coalesced across lanes
            xr[i] = v.x; xi[i] = v.y;
        }

        // full A (scale-free covariance) for the projector math
        float Ar[4][4], Ai[4][4];
        #pragma unroll
        for (int c = 0; c < 4; c++)
            #pragma unroll
            for (int d = 0; d <= c; d++) {
                float sr = 0.f, si = 0.f;
                #pragma unroll
                for (int t = 0; t < 4; t++) {
                    int ic = t * 4 + c, id = t * 4 + d;
                    sr = fmaf(xr[ic], xr[id], fmaf(xi[ic], xi[id], sr));
                    si = fmaf(xi[ic], xr[id], fmaf(-xr[ic], xi[id], si));
                }
                Ar[c][d] = sr;  Ai[c][d] = (c == d) ? 0.f : si;
                Ar[d][c] = sr;  Ai[d][c] = -Ai[c][d];
            }

        // compact working copy: diag + upper triangle
        float d0 = Ar[0][0], d1 = Ar[1][1], d2 = Ar[2][2], d3 = Ar[3][3];
        float u01r = Ar[0][1], u01i = Ai[0][1];
        float u02r = Ar[0][2], u02i = Ai[0][2];
        float u03r = Ar[0][3], u03i = Ai[0][3];
        float u12r = Ar[1][2], u12i = Ai[1][2];
        float u13r = Ar[1][3], u13i = Ai[1][3];
        float u23r = Ar[2][3], u23i = Ai[2][3];

        float trace = d0 + d1 + d2 + d3;
        float thr   = trace * trace * 1e-14f + 1e-30f;

        for (int sweep = 0; sweep < 5; sweep++) {
            ROTC(d0,d1,u01r,u01i, OFF_B(u02r,u02i,u12r,u12i) OFF_B(u03r,u03i,u13r,u13i));
            ROTC(d2,d3,u23r,u23i, OFF_A(u02r,u02i,u03r,u03i) OFF_A(u12r,u12i,u13r,u13i));
            ROTC(d0,d2,u02r,u02i, OFF_C(u01r,u01i,u12r,u12i) OFF_B(u03r,u03i,u23r,u23i));
            ROTC(d1,d3,u13r,u13i, OFF_A(u01r,u01i,u03r,u03i) OFF_C(u12r,u12i,u23r,u23i));
            ROTC(d0,d3,u03r,u03i, OFF_C(u01r,u01i,u13r,u13i) OFF_C(u02r,u02i,u23r,u23i));
            ROTC(d1,d2,u12r,u12i, OFF_A(u01r,u01i,u02r,u02i) OFF_B(u13r,u13i,u23r,u23i));
        }

        // sort eigenvalues lam0<=lam1<=lam2<=lam3 via rank
        float ev0 = d0, ev1 = d1, ev2 = d2, ev3 = d3;
        int r0 = (ev1 <  ev0) + (ev2 <  ev0) + (ev3 <  ev0);
        int r1 = (ev0 <= ev1) + (ev2 <  ev1) + (ev3 <  ev1);
        int r2 = (ev0 <= ev2) + (ev1 <= ev2) + (ev3 <  ev2);
        int r3 = (ev0 <= ev3) + (ev1 <= ev3) + (ev2 <= ev3);
        float lam0 = (r0==0)?ev0:((r1==0)?ev1:((r2==0)?ev2:ev3));
        float lam1 = (r0==1)?ev0:((r1==1)?ev1:((r2==1)?ev2:ev3));
        float lam2 = (r0==2)?ev0:((r1==2)?ev1:((r2==2)?ev2:ev3));
        float lam3 = (r0==3)?ev0:((r1==3)?ev1:((r2==3)?ev2:ev3));

        // p(x) = (x-lam3)(x-lam2);  P_noise = p(A) * (alpha*A + beta*I)
        float s  = lam3 + lam2;
        float tp = lam3 * lam2;
        float pc = (lam0 - lam3) * (lam0 - lam2);
        float pd = (lam1 - lam3) * (lam1 - lam2);
        float alpha = __fdividef(s - lam0 - lam1, pc * pd);
        float beta  = __fdividef(1.f, pc) - alpha * lam0;

        // B = A^2 - s*A + tp*I
        float Br[4][4], Bi[4][4];
        #pragma unroll
        for (int i = 0; i < 4; i++)
            #pragma unroll
            for (int j = 0; j < 4; j++) {
                float br = 0.f, bi = 0.f;
                #pragma unroll
                for (int k = 0; k < 4; k++) {
                    br = fmaf(Ar[i][k], Ar[k][j], fmaf(-Ai[i][k], Ai[k][j], br));
                    bi = fmaf(Ar[i][k], Ai[k][j], fmaf( Ai[i][k], Ar[k][j], bi));
                }
                br = fmaf(-s, Ar[i][j], br);
                bi = fmaf(-s, Ai[i][j], bi);
                if (i == j) br += tp;
                Br[i][j] = br; Bi[i][j] = bi;
            }

        // P[c][d] = alpha*(B*A)[c][d] + beta*B[c][d]
        #define PAE(c, d, RR, II)                                              \
            float RR = 0.f, II = 0.f;                                          \
            _Pragma("unroll")                                                  \
            for (int k2 = 0; k2 < 4; k2++) {                                   \
                RR = fmaf(Br[c][k2], Ar[k2][d], fmaf(-Bi[c][k2], Ai[k2][d], RR)); \
                II = fmaf(Br[c][k2], Ai[k2][d], fmaf( Bi[c][k2], Ar[k2][d], II)); \
            }                                                                  \
            RR = fmaf(alpha, RR, beta * Br[c][d]);                             \
            II = fmaf(alpha, II, beta * Bi[c][d]);
        PAE(1,0, Pr10, Pi10) PAE(2,1, Pr21, Pi21) PAE(3,2, Pr32, Pi32)
        PAE(2,0, Pr20, Pi20) PAE(3,1, Pr31, Pi31) PAE(3,0, Pr30, Pi30)
        #undef PAE

        float trBA = 0.f;
        #pragma unroll
        for (int i = 0; i < 4; i++)
            #pragma unroll
            for (int k = 0; k < 4; k++)
                trBA = fmaf(Br[i][k], Ar[i][k], fmaf(Bi[i][k], Ai[i][k], trBA));
        float q0 = fmaf(alpha, trBA, beta * (Br[0][0] + Br[1][1] + Br[2][2] + Br[3][3]));

        float* qo = &sQ[f * 8];
        qo[0] = q0;
        qo[1] = Pr10 + Pr21 + Pr32;
        qo[2] = Pi10 + Pi21 + Pi32;
        qo[3] = Pr20 + Pr31;
        qo[4] = Pi20 + Pi31;
        qo[5] = Pr30;
        qo[6] = Pi30;
        qo[7] = 0.f;
    }
    __syncthreads();

    // ---------- reset bookkeeping for the next graph replay ----------
    if (tid == 0) {
        unsigned int r = atomicAdd(&g_done, 1u);
        if (r == (unsigned)(NBLK - 1)) {     // last block past the poll: reset
            *(volatile unsigned int*)&g_cnt  = 0u;
            *(volatile unsigned int*)&g_done = 0u;
        }
    }

    // ---------- phase 3: spectrum ----------
    if (a < NANG) {
        float acc = 0.0f;
        float c1 = c1a, s1 = s1a;
        #pragma unroll
        for (int k = 0; k < NBIN; k++) {
            float c2 = fmaf(c1, c1, -s1*s1);
            float s2 = 2.0f * c1 * s1;
            float c3 = fmaf(c2, c1, -s2*s1);
            float s3 = fmaf(s2, c1,  c2*s1);
            const float* q = &sQ[k * 8];
            float denom = fmaf(2.0f,
                  fmaf(q[1], c1, fmaf(q[2], s1,
                  fmaf(q[3], c2, fmaf(q[4], s2,
                  fmaf(q[5], c3,       q[6]*s3))))),
                  q[0]) + 1e-8f;
            acc += __fdividef(1.0f, denom);
            float c1n = fmaf(c1, cda, -s1*sda);
            float s1n = fmaf(s1, cda,  c1*sda);
            c1 = c1n; s1 = s1n;
        }
        out[a] = acc * (1.0f / 19.0f);
    }
}

extern "C" void kernel_launch(void* const* d_in, const int* in_sizes, int n_in,
                              void* d_out, int out_size)
{
    const float* x = (const float*)d_in[0];
    float* out = (float*)d_out;
    k_music<<<NBLK, NTHR>>>(x, out);
}

// round 17
// speedup vs baseline: 1.2732x; 1.2732x over previous
#include <cuda_runtime.h>
#include <math.h>

// ---- problem constants ----
#define NFFT      512
#define HOP       256
#define NBIN      19      // rfft bins 13..31  (400 <= f < 1000 Hz, df = 31.25)
#define BIN0      13
#define NANG      18001
#define MICS      4
#define NFRM      4       // EST_NUM frames, t = 120..123
#define SAMPLE_OFF 30464  // first sample used = 119*256
#define NTCK      (NFRM * MICS * NBIN)   // 304

// DFT results X[t][c][k], layout (t*MICS+c)*NBIN + k
__device__ float2 gX[NTCK];

// ============================================================
// Kernel 1: warp-parallel windowed DFT. One warp per (t,c,bin).
// 38 blocks x 256 threads = 304 warps.  (proven fast)
// ============================================================
__global__ void __launch_bounds__(256, 1) k_dft(const float* __restrict__ x)
{
    const int w = (blockIdx.x * 256 + threadIdx.x) >> 5;   // 0..303 exactly
    const int l = threadIdx.x & 31;

    const int t   = w / (MICS * NBIN);
    const int rem = w % (MICS * NBIN);
    const int c   = rem / NBIN;
    const int bin = (rem % NBIN) + BIN0;

    const float ANG = -0.012271846303085130f;              // -2*pi/512
    float c1, s1, cs, ss;
    __sincosf((float)((bin * l)  & 511) * ANG, &s1, &c1);
    __sincosf((float)((bin * 32) & 511) * ANG, &ss, &cs);

    const float* px = x + ((size_t)SAMPLE_OFF + (size_t)t * HOP) * MICS + c;

    float re = 0.f, im = 0.f;
    #pragma unroll
    for (int j = 0; j < 16; j++) {
        int n = l + 32 * j;
        float v = px[n * MICS] * __sinf((float)n * (float)(M_PI / 512.0));
        re = fmaf(v, c1, re);
        im = fmaf(v, s1, im);
        float cn = fmaf(c1, cs, -s1 * ss);
        float sn = fmaf(s1, cs,  c1 * ss);
        c1 = cn; s1 = sn;
    }
    #pragma unroll
    for (int off = 16; off; off >>= 1) {
        re += __shfl_down_sync(0xffffffffu, re, off);
        im += __shfl_down_sync(0xffffffffu, im, off);
    }
    if (l == 0) gX[w] = make_float2(re, im);
}

// ---- Hermitian-compact complex Jacobi (eigenvalues only) ----
// Pattern A: stored (u_{ip}, u_{iq}), i < p < q
#define OFF_A(U1R,U1I,U2R,U2I) { \
    float t1r =  cc*U1R + ser*U2R + sei*U2I; \
    float t1i =  cc*U1I + ser*U2I - sei*U2R; \
    float t2r = -ssn*U1R + cer*U2R + cei*U2I; \
    float t2i = -ssn*U1I + cer*U2I - cei*U2R; \
    U1R=t1r; U1I=t1i; U2R=t2r; U2I=t2i; }
// Pattern B: stored (u_{pi}, u_{qi}), p < q < i
#define OFF_B(U1R,U1I,U2R,U2I) { \
    float t1r =  cc*U1R + ser*U2R - sei*U2I; \
    float t1i =  cc*U1I + ser*U2I + sei*U2R; \
    float t2r = -ssn*U1R + cer*U2R - cei*U2I; \
    float t2i = -ssn*U1I + cer*U2I + cei*U2R; \
    U1R=t1r; U1I=t1i; U2R=t2r; U2I=t2i; }
// Pattern C: stored (u_{pi}, u_{iq}), p < i < q
#define OFF_C(U1R,U1I,U2R,U2I) { \
    float t1r =  cc*U1R + ser*U2R + sei*U2I; \
    float t1i =  cc*U1I - ser*U2I + sei*U2R; \
    float t2r = -ssn*U1R + cer*U2R + cei*U2I; \
    float t2i =  ssn*U1I + cer*U2I - cei*U2R; \
    U1R=t1r; U1I=t1i; U2R=t2r; U2I=t2i; }

// rotation on pair (p,q). Diagonal update via the numerically stable
// standard form:  d_p' = d_p + t*g,  d_q' = d_q - t*g   (t = tan(theta))
#define ROTC(DP,DQ,UR,UI,OFF) do { \
    float gr=UR, gi=UI; \
    float g2=fmaf(gr,gr,gi*gi); \
    if (g2>=thr) { \
        float inv_g=rsqrtf(g2); float g=g2*inv_g; \
        float er=gr*inv_g, ei=gi*inv_g; \
        float tau=(DQ-DP)*(0.5f*inv_g); \
        float t2v=fmaf(tau,tau,1.f); float root=t2v*rsqrtf(t2v); \
        float tt=__fdividef((tau>=0.f)?-1.f:1.f, fabsf(tau)+root); \
        float cc=rsqrtf(fmaf(tt,tt,1.f)); float ssn=tt*cc; \
        float ser=ssn*er, sei=ssn*ei, cer=cc*er, cei=cc*ei; \
        float tg=tt*g; \
        DP=DP+tg; DQ=DQ-tg; UR=0.f; UI=0.f; \
        OFF \
    } } while(0)

// ============================================================
// Kernel 2 (fused): lanes 0..18 of warp 0 in every block compute
// the 19 noise projectors via compact eigenvalues-only Jacobi +
// polynomial projector P = p(A)(aA+bI); then all threads evaluate
// their angle of the MUSIC spectrum.
// ============================================================
__global__ void __launch_bounds__(128, 1) k_eig_spec(float* __restrict__ out)
{
    __shared__ float sQ[NBIN * 8];
    const int tid = threadIdx.x;

    if (tid < NBIN) {
        const int f = tid;
        float xr[16], xi[16];
        #pragma unroll
        for (int i = 0; i < 16; i++) {
            float2 v = __ldcg(&gX[i * NBIN + f]);   // coalesced across lanes
            xr[i] = v.x; xi[i] = v.y;
        }

        // A[c][d] = sum_t X[t][c] conj(X[t][d])  (scale-free)
        float Ar[4][4], Ai[4][4];
        #pragma unroll
        for (int c = 0; c < 4; c++)
            #pragma unroll
            for (int d = 0; d <= c; d++) {
                float sr = 0.f, si = 0.f;
                #pragma unroll
                for (int t = 0; t < 4; t++) {
                    int ic = t * 4 + c, id = t * 4 + d;
                    sr = fmaf(xr[ic], xr[id], fmaf(xi[ic], xi[id], sr));
                    si = fmaf(xi[ic], xr[id], fmaf(-xr[ic], xi[id], si));
                }
                Ar[c][d] = sr;  Ai[c][d] = (c == d) ? 0.f : si;
                Ar[d][c] = sr;  Ai[d][c] = -Ai[c][d];
            }

        // compact working copy: diag + upper triangle
        float d0 = Ar[0][0], d1 = Ar[1][1], d2 = Ar[2][2], d3 = Ar[3][3];
        float u01r = Ar[0][1], u01i = Ai[0][1];
        float u02r = Ar[0][2], u02i = Ai[0][2];
        float u03r = Ar[0][3], u03i = Ai[0][3];
        float u12r = Ar[1][2], u12i = Ai[1][2];
        float u13r = Ar[1][3], u13i = Ai[1][3];
        float u23r = Ar[2][3], u23i = Ai[2][3];

        float trace = d0 + d1 + d2 + d3;
        float thr   = trace * trace * 1e-14f + 1e-30f;

        for (int sweep = 0; sweep < 5; sweep++) {
            ROTC(d0,d1,u01r,u01i, OFF_B(u02r,u02i,u12r,u12i) OFF_B(u03r,u03i,u13r,u13i));
            ROTC(d2,d3,u23r,u23i, OFF_A(u02r,u02i,u03r,u03i) OFF_A(u12r,u12i,u13r,u13i));
            ROTC(d0,d2,u02r,u02i, OFF_C(u01r,u01i,u12r,u12i) OFF_B(u03r,u03i,u23r,u23i));
            ROTC(d1,d3,u13r,u13i, OFF_A(u01r,u01i,u03r,u03i) OFF_C(u12r,u12i,u23r,u23i));
            ROTC(d0,d3,u03r,u03i, OFF_C(u01r,u01i,u13r,u13i) OFF_C(u02r,u02i,u23r,u23i));
            ROTC(d1,d2,u12r,u12i, OFF_A(u01r,u01i,u02r,u02i) OFF_B(u13r,u13i,u23r,u23i));
        }

        // sort eigenvalues lam0<=lam1<=lam2<=lam3 via rank
        float ev0 = d0, ev1 = d1, ev2 = d2, ev3 = d3;
        int r0 = (ev1 <  ev0) + (ev2 <  ev0) + (ev3 <  ev0);
        int r1 = (ev0 <= ev1) + (ev2 <  ev1) + (ev3 <  ev1);
        int r2 = (ev0 <= ev2) + (ev1 <= ev2) + (ev3 <  ev2);
        int r3 = (ev0 <= ev3) + (ev1 <= ev3) + (ev2 <= ev3);
        float lam0 = (r0==0)?ev0:((r1==0)?ev1:((r2==0)?ev2:ev3));
        float lam1 = (r0==1)?ev0:((r1==1)?ev1:((r2==1)?ev2:ev3));
        float lam2 = (r0==2)?ev0:((r1==2)?ev1:((r2==2)?ev2:ev3));
        float lam3 = (r0==3)?ev0:((r1==3)?ev1:((r2==3)?ev2:ev3));

        // p(x) = (x-lam3)(x-lam2);  P_noise = p(A) * (alpha*A + beta*I)
        float s  = lam3 + lam2;
        float tp = lam3 * lam2;
        float pc = (lam0 - lam3) * (lam0 - lam2);
        float pd = (lam1 - lam3) * (lam1 - lam2);
        float alpha = __fdividef(s - lam0 - lam1, pc * pd);
        float beta  = __fdividef(1.f, pc) - alpha * lam0;

        // B = A^2 - s*A + tp*I
        float Br[4][4], Bi[4][4];
        #pragma unroll
        for (int i = 0; i < 4; i++)
            #pragma unroll
            for (int j = 0; j < 4; j++) {
                float br = 0.f, bi = 0.f;
                #pragma unroll
                for (int k = 0; k < 4; k++) {
                    br = fmaf(Ar[i][k], Ar[k][j], fmaf(-Ai[i][k], Ai[k][j], br));
                    bi = fmaf(Ar[i][k], Ai[k][j], fmaf( Ai[i][k], Ar[k][j], bi));
                }
                br = fmaf(-s, Ar[i][j], br);
                bi = fmaf(-s, Ai[i][j], bi);
                if (i == j) br += tp;
                Br[i][j] = br; Bi[i][j] = bi;
            }

        // P[c][d] = alpha*(B*A)[c][d] + beta*B[c][d]
        #define PAE(c, d, RR, II)                                              \
            float RR = 0.f, II = 0.f;                                          \
            _Pragma("unroll")                                                  \
            for (int k2 = 0; k2 < 4; k2++) {                                   \
                RR = fmaf(Br[c][k2], Ar[k2][d], fmaf(-Bi[c][k2], Ai[k2][d], RR)); \
                II = fmaf(Br[c][k2], Ai[k2][d], fmaf( Bi[c][k2], Ar[k2][d], II)); \
            }                                                                  \
            RR = fmaf(alpha, RR, beta * Br[c][d]);                             \
            II = fmaf(alpha, II, beta * Bi[c][d]);
        PAE(1,0, Pr10, Pi10) PAE(2,1, Pr21, Pi21) PAE(3,2, Pr32, Pi32)
        PAE(2,0, Pr20, Pi20) PAE(3,1, Pr31, Pi31) PAE(3,0, Pr30, Pi30)
        #undef PAE

        float trBA = 0.f;
        #pragma unroll
        for (int i = 0; i < 4; i++)
            #pragma unroll
            for (int k = 0; k < 4; k++)
                trBA = fmaf(Br[i][k], Ar[i][k], fmaf(Bi[i][k], Ai[i][k], trBA));
        float q0 = fmaf(alpha, trBA, beta * (Br[0][0] + Br[1][1] + Br[2][2] + Br[3][3]));

        float* qo = &sQ[f * 8];
        qo[0] = q0;
        qo[1] = Pr10 + Pr21 + Pr32;
        qo[2] = Pi10 + Pi21 + Pi32;
        qo[3] = Pr20 + Pr31;
        qo[4] = Pi20 + Pi31;
        qo[5] = Pr30;
        qo[6] = Pi30;
        qo[7] = 0.f;
    }

    // ---- spec init (independent of sQ; overlaps warp 0's eigen) ----
    int a = blockIdx.x * 128 + tid;
    float th = (-90.0f + 0.01f * (float)a) * 0.017453292519943295f;
    float st = __sinf(th);
    float base = (float)(2.0 * M_PI * 0.1 / 343.0) * st;
    float dphi = base * 31.25f;
    float phi0 = dphi * (float)BIN0;
    float s1, c1, sd, cd;
    __sincosf(phi0, &s1, &c1);
    __sincosf(dphi, &sd, &cd);

    __syncthreads();

    if (a >= NANG) return;

    float acc = 0.0f;
    #pragma unroll
    for (int k = 0; k < NBIN; k++) {
        float c2 = fmaf(c1, c1, -s1*s1);
        float s2 = 2.0f * c1 * s1;
        float c3 = fmaf(c2, c1, -s2*s1);
        float s3 = fmaf(s2, c1,  c2*s1);
        const float* q = &sQ[k * 8];
        float denom = fmaf(2.0f,
              fmaf(q[1], c1, fmaf(q[2], s1,
              fmaf(q[3], c2, fmaf(q[4], s2,
              fmaf(q[5], c3,       q[6]*s3))))),
              q[0]) + 1e-8f;
        acc += __fdividef(1.0f, denom);
        float c1n = fmaf(c1, cd, -s1*sd);
        float s1n = fmaf(s1, cd,  c1*sd);
        c1 = c1n; s1 = s1n;
    }
    out[a] = acc * (1.0f / 19.0f);
}

extern "C" void kernel_launch(void* const* d_in, const int* in_sizes, int n_in,
                              void* d_out, int out_size)
{
    const float* x = (const float*)d_in[0];
    float* out = (float*)d_out;
    k_dft<<<38, 256>>>(x);
    k_eig_spec<<<(NANG + 127) / 128, 128>>>(out);
}